// round 2
// baseline (speedup 1.0000x reference)
#include <cuda_runtime.h>

#define E_CNT 100000
#define NDST  10000
#define CDIM  128
#define OUTC  2048

// ---------------- small scratch only (CSR) ----------------
__device__ int g_counts  [NDST];
__device__ int g_rowstart[NDST];
__device__ int g_cursor  [NDST];
__device__ int g_eid     [E_CNT];

__global__ void zero_cnt_k() {
    int i = blockIdx.x * blockDim.x + threadIdx.x;
    if (i < NDST) g_counts[i] = 0;
}

__global__ void hist_k(const int* __restrict__ dst) {
    int e = blockIdx.x * blockDim.x + threadIdx.x;
    if (e < E_CNT) atomicAdd(&g_counts[dst[e]], 1);
}

__global__ void scan_k() {
    __shared__ int ss[1024];
    const int tid = threadIdx.x;
    const int CH = 10;
    int base = tid * CH;
    int loc[CH];
    int s = 0;
#pragma unroll
    for (int i = 0; i < CH; i++) {
        int idx = base + i;
        int v = (idx < NDST) ? g_counts[idx] : 0;
        loc[i] = s;
        s += v;
    }
    ss[tid] = s;
    __syncthreads();
    for (int off = 1; off < 1024; off <<= 1) {
        int v = 0;
        if (tid >= off) v = ss[tid - off];
        __syncthreads();
        if (tid >= off) ss[tid] += v;
        __syncthreads();
    }
    int excl = (tid == 0) ? 0 : ss[tid - 1];
#pragma unroll
    for (int i = 0; i < CH; i++) {
        int idx = base + i;
        if (idx < NDST) {
            int r = excl + loc[i];
            g_rowstart[idx] = r;
            g_cursor[idx]   = r;
        }
    }
}

__global__ void fill_k(const int* __restrict__ dst) {
    int e = blockIdx.x * blockDim.x + threadIdx.x;
    if (e < E_CNT) {
        int p = atomicAdd(&g_cursor[dst[e]], 1);
        g_eid[p] = e;
    }
}

__global__ void zero_out_k(float4* __restrict__ out, int n4) {
    int i = blockIdx.x * blockDim.x + threadIdx.x;
    if (i < n4) out[i] = make_float4(0.f, 0.f, 0.f, 0.f);
}

// ---------------- fused MLP + tensor-product + segment-sum ----------------
// 64 CSR-ordered edges per block, 256 threads.
// smem floats: Hs 8192 | Xs 8192 | Ws 4096 (W2 chunk / EMBs) | TPWs 8192 (tpw / W1s) | SHs 1024 | 192 ints
#define SMEM_BYTES (((64*128)*3 + 32*128 + 64*16) * 4 + 192 * 4)

__global__ __launch_bounds__(256) void fused_k(
    const float* __restrict__ src_features,
    const float* __restrict__ edge_sh,
    const float* __restrict__ edge_emb,
    const float* __restrict__ W1,
    const float* __restrict__ W2,
    const int*   __restrict__ src,
    const int*   __restrict__ dst,
    float*       __restrict__ out)
{
    extern __shared__ float smem[];
    float* Hs   = smem;                 // [64][128]
    float* Xs   = Hs + 64 * 128;        // [64][128]
    float* Ws   = Xs + 64 * 128;        // [32][128] W2 chunk; aliases EMBs [64][64]
    float* TPWs = Ws + 32 * 128;        // [64][128]; aliases W1s [64][128]
    float* SHs  = TPWs + 64 * 128;      // [64][16]
    int*   Ds   = (int*)(SHs + 64 * 16);
    int*   Es   = Ds + 64;
    int*   Ss   = Es + 64;

    float* EMBs = Ws;
    float* W1s  = TPWs;

    const int tid = threadIdx.x;
    const int tr  = tid >> 5;   // 0..7  (edge group of 8)
    const int tc  = tid & 31;   // 0..31 (col group of 4)

    const int pos0 = blockIdx.x * 64;
    const int nE   = (E_CNT - pos0 < 64) ? (E_CNT - pos0) : 64;

    // ---- stage edge metadata ----
    if (tid < 64) {
        int sl = (tid < nE) ? tid : (nE - 1);
        int e  = g_eid[pos0 + sl];
        Es[tid] = e;
        Ss[tid] = src[e];
        Ds[tid] = dst[e];
    }
    __syncthreads();

    // ---- stage EMBs (gathered), W1s (scaled), Xs (gathered), SHs (pad->0) ----
#pragma unroll
    for (int t = 0; t < 4; t++) {            // EMBs: 64 x 16 float4
        int li = tid + t * 256;
        int slot = li >> 4, f = li & 15;
        reinterpret_cast<float4*>(EMBs)[li] =
            reinterpret_cast<const float4*>(edge_emb)[(size_t)Es[slot] * 16 + f];
    }
#pragma unroll
    for (int t = 0; t < 8; t++) {            // W1s: 64 x 32 float4, * 1/8
        int li = tid + t * 256;
        float4 v = reinterpret_cast<const float4*>(W1)[li];
        v.x *= 0.125f; v.y *= 0.125f; v.z *= 0.125f; v.w *= 0.125f;
        reinterpret_cast<float4*>(W1s)[li] = v;
    }
#pragma unroll
    for (int t = 0; t < 8; t++) {            // Xs: 64 x 32 float4
        int li = tid + t * 256;
        int slot = li >> 5, f = li & 31;
        reinterpret_cast<float4*>(Xs)[li] =
            reinterpret_cast<const float4*>(src_features)[(size_t)Ss[slot] * 32 + f];
    }
    {                                        // SHs: 64 x 4 float4 (zero pads)
        int slot = tid >> 2, f = tid & 3;
        float4 v = make_float4(0.f, 0.f, 0.f, 0.f);
        if (slot < nE)
            v = reinterpret_cast<const float4*>(edge_sh)[(size_t)Es[slot] * 4 + f];
        reinterpret_cast<float4*>(SHs)[tid] = v;
    }
    __syncthreads();

    // ---- GEMM1: Hs = silu(EMBs @ W1s), 64x128x64 ----
    {
        float acc[8][4];
#pragma unroll
        for (int i = 0; i < 8; i++)
#pragma unroll
            for (int j = 0; j < 4; j++) acc[i][j] = 0.f;

#pragma unroll 16
        for (int kk = 0; kk < 64; kk++) {
            float4 rb = reinterpret_cast<const float4*>(W1s + kk * 128)[tc];
#pragma unroll
            for (int i = 0; i < 8; i++) {
                float ra = EMBs[(tr * 8 + i) * 64 + kk];
                acc[i][0] += ra * rb.x; acc[i][1] += ra * rb.y;
                acc[i][2] += ra * rb.z; acc[i][3] += ra * rb.w;
            }
        }
#pragma unroll
        for (int i = 0; i < 8; i++) {
            float4 v;
            v.x = acc[i][0]; v.y = acc[i][1]; v.z = acc[i][2]; v.w = acc[i][3];
            v.x = v.x / (1.f + __expf(-v.x));
            v.y = v.y / (1.f + __expf(-v.y));
            v.z = v.z / (1.f + __expf(-v.z));
            v.w = v.w / (1.f + __expf(-v.w));
            reinterpret_cast<float4*>(Hs + (tr * 8 + i) * 128)[tc] = v;
        }
    }
    __syncthreads();

    // ---- per-l: GEMM2 tile + fold x + run-length segment scatter ----
    const float w2s = 0.08838834764831845f;  // 1/sqrt(128)

    for (int l = 0; l < 4; l++) {
        const int d    = 2 * l + 1;
        const int soff = l * l;                            // 0,1,4,9
        const int ob   = (l == 0) ? 0 : (l == 1) ? 128 : (l == 2) ? 512 : 1152;

        float acc[8][4];
#pragma unroll
        for (int i = 0; i < 8; i++)
#pragma unroll
            for (int j = 0; j < 4; j++) acc[i][j] = 0.f;

        for (int k0 = 0; k0 < 128; k0 += 32) {
            __syncthreads();                               // Ws reuse guard
#pragma unroll
            for (int t = 0; t < 4; t++) {                  // load W2 chunk 32x128
                int li = tid + t * 256;
                int r = li >> 5, f = li & 31;
                float4 v = reinterpret_cast<const float4*>(
                    W2 + (size_t)(k0 + r) * 512 + l * 128)[f];
                v.x *= w2s; v.y *= w2s; v.z *= w2s; v.w *= w2s;
                reinterpret_cast<float4*>(Ws)[li] = v;
            }
            __syncthreads();
#pragma unroll
            for (int kk = 0; kk < 32; kk++) {
                float4 rb = reinterpret_cast<const float4*>(Ws + kk * 128)[tc];
#pragma unroll
                for (int i = 0; i < 8; i++) {
                    float ra = Hs[(tr * 8 + i) * 128 + k0 + kk];
                    acc[i][0] += ra * rb.x; acc[i][1] += ra * rb.y;
                    acc[i][2] += ra * rb.z; acc[i][3] += ra * rb.w;
                }
            }
        }
        __syncthreads();                                   // phase2(l-1) done everywhere
#pragma unroll
        for (int i = 0; i < 8; i++) {                      // TPWs = acc * x
            float4 xv = reinterpret_cast<const float4*>(Xs + (tr * 8 + i) * 128)[tc];
            float4 v;
            v.x = acc[i][0] * xv.x; v.y = acc[i][1] * xv.y;
            v.z = acc[i][2] * xv.z; v.w = acc[i][3] * xv.w;
            reinterpret_cast<float4*>(TPWs + (tr * 8 + i) * 128)[tc] = v;
        }
        __syncthreads();

        // phase 2: per output column (c,s), run-length reduce over dst-sorted edges
        const int ncol = 128 * d;
        for (int q = tid; q < ncol; q += 256) {
            const int c = q / d;
            const int s = q - c * d;
            float a = 0.f;
            int cur = Ds[0];
#pragma unroll 8
            for (int t = 0; t < 64; t++) {
                int dn = Ds[t];
                if (dn != cur) {
                    atomicAdd(&out[(size_t)cur * OUTC + ob + q], a);
                    a = 0.f;
                    cur = dn;
                }
                a += TPWs[t * 128 + c] * SHs[t * 16 + soff + s];
            }
            atomicAdd(&out[(size_t)cur * OUTC + ob + q], a);
        }
        __syncthreads();
    }
}

// ---------------- launch ----------------
extern "C" void kernel_launch(void* const* d_in, const int* in_sizes, int n_in,
                              void* d_out, int out_size)
{
    const float* src_features = (const float*)d_in[0];
    const float* edge_sh      = (const float*)d_in[1];
    const float* edge_emb     = (const float*)d_in[2];
    const float* W1           = (const float*)d_in[3];
    const float* W2           = (const float*)d_in[4];
    const int*   src          = (const int*)d_in[5];
    const int*   dst          = (const int*)d_in[6];
    float*       out          = (float*)d_out;
    (void)in_sizes; (void)n_in; (void)out_size;

    static bool attr_done = false;
    if (!attr_done) {
        cudaFuncSetAttribute(fused_k, cudaFuncAttributeMaxDynamicSharedMemorySize,
                             SMEM_BYTES);
        attr_done = true;
    }

    // CSR build
    zero_cnt_k<<<(NDST + 255) / 256, 256>>>();
    hist_k<<<(E_CNT + 255) / 256, 256>>>(dst);
    scan_k<<<1, 1024>>>();
    fill_k<<<(E_CNT + 255) / 256, 256>>>(dst);

    // zero output (atomic accumulation target)
    const int n4 = NDST * OUTC / 4;
    zero_out_k<<<(n4 + 255) / 256, 256>>>((float4*)out, n4);

    // fused MLP + TP + scatter
    const int nblk = (E_CNT + 63) / 64;
    fused_k<<<nblk, 256, SMEM_BYTES>>>(src_features, edge_sh, edge_emb,
                                       W1, W2, src, dst, out);
}